// round 15
// baseline (speedup 1.0000x reference)
#include <cuda_runtime.h>
#include <cuda_fp16.h>
#include <cuda_bf16.h>
#include <cstdint>
#include <cstddef>

#define NN    20000
#define EE    320000
#define ET    340000
#define BB    64
#define IND   768
#define H1D   512
#define NHEADS 4
#define HIDC  128
#define OUTD  256
#define SMAX  192

// ---------------- scratch (device globals) ----------------------------------
__device__ __half g_h  [(size_t)NN * H1D];
__device__ __half g_fh [(size_t)NN * H1D];
__device__ float g_feat[(size_t)NN * OUTD];
__device__ __nv_bfloat16 g_ahi[(size_t)NN * IND];
__device__ __nv_bfloat16 g_alo[(size_t)NN * IND];
__device__ __nv_bfloat16 g_whi[(size_t)IND * H1D];
__device__ __nv_bfloat16 g_wlo[(size_t)IND * H1D];
__device__ float g_ssrc[NN * NHEADS];
__device__ float g_sdst[NN * NHEADS];
__device__ float g_bn  [2 * H1D];
__device__ float g_cnt [BB];
__device__ int   g_deg [NN];
__device__ int   g_row [NN + 1];
__device__ int   g_cur [NN];
__device__ int   g_srcs[ET];

__device__ __forceinline__ float lrelu(float v) { return v > 0.f ? v : 0.2f * v; }

__device__ __forceinline__ void split_bf(float v, __nv_bfloat16& h, __nv_bfloat16& l) {
    h = __float2bfloat16(v);
    l = __float2bfloat16(v - __bfloat162float(h));
}

#define LDSM4(r0, r1, r2, r3, addr) \
    asm volatile("ldmatrix.sync.aligned.m8n8.x4.shared.b16 {%0,%1,%2,%3}, [%4];" \
        : "=r"(r0), "=r"(r1), "=r"(r2), "=r"(r3) : "r"(addr))

#define MMA_BF16(d, a, b) \
    asm volatile("mma.sync.aligned.m16n8k16.row.col.f32.bf16.bf16.f32 " \
        "{%0,%1,%2,%3}, {%4,%5,%6,%7}, {%8,%9}, {%0,%1,%2,%3};" \
        : "+f"((d)[0]), "+f"((d)[1]), "+f"((d)[2]), "+f"((d)[3]) \
        : "r"((a)[0]), "r"((a)[1]), "r"((a)[2]), "r"((a)[3]), "r"((b)[0]), "r"((b)[1]))

__device__ __forceinline__ uint32_t smem_u32(const void* p) {
    uint32_t a;
    asm("{ .reg .u64 t; cvta.to.shared.u64 t, %1; cvt.u32.u64 %0, t; }" : "=r"(a) : "l"(p));
    return a;
}

// ---------------- prep1: W1 transpose+split AND x split (fused) --------------
#define T1BLK ((H1D / 32) * (IND / 32))
#define SPLBLK ((NN * IND / 4 + 255) / 256)
__global__ void prep1_k(const float* __restrict__ W,
                        __nv_bfloat16* __restrict__ whi, __nv_bfloat16* __restrict__ wlo,
                        const float* __restrict__ x,
                        __nv_bfloat16* __restrict__ ahi, __nv_bfloat16* __restrict__ alo)
{
    __shared__ float t[32][33];
    int bid = blockIdx.x;
    int tx = threadIdx.x, ty = threadIdx.y;
    if (bid < T1BLK) {
        int bx = bid % (H1D / 32);
        int by = bid / (H1D / 32);
        int xcol = bx * 32 + tx;
        int y0 = by * 32;
        for (int i = ty; i < 32; i += 8)
            t[i][tx] = W[(size_t)(y0 + i) * H1D + xcol];
        __syncthreads();
        int xo = y0 + tx;
        int yo0 = bx * 32;
        for (int i = ty; i < 32; i += 8) {
            __nv_bfloat16 h, l;
            split_bf(t[tx][i], h, l);
            whi[(size_t)(yo0 + i) * IND + xo] = h;
            wlo[(size_t)(yo0 + i) * IND + xo] = l;
        }
    } else {
        int i = ((bid - T1BLK) * 256 + ty * 32 + tx) * 4;
        if (i < NN * IND) {
            float4 v = *(const float4*)(x + i);
            __nv_bfloat16 h0, l0, h1, l1, h2, l2, h3, l3;
            split_bf(v.x, h0, l0); split_bf(v.y, h1, l1);
            split_bf(v.z, h2, l2); split_bf(v.w, h3, l3);
            ahi[i] = h0; ahi[i + 1] = h1; ahi[i + 2] = h2; ahi[i + 3] = h3;
            alo[i] = l0; alo[i + 1] = l1; alo[i + 2] = l2; alo[i + 3] = l3;
        }
    }
}

// ---------------- CSR build --------------------------------------------------
__global__ void deg_k(const int* __restrict__ ei) {
    int e = blockIdx.x * blockDim.x + threadIdx.x;
    if (e >= ET) return;
    int d = (e < EE) ? ei[EE + e] : (e - EE);
    atomicAdd(&g_deg[d], 1);
}
#define SCHK 20
__global__ __launch_bounds__(1024) void scan_k() {
    __shared__ int s[1024];
    int t = threadIdx.x;
    int base = t * SCHK;
    int local[SCHK];
    int sum = 0;
    #pragma unroll
    for (int i = 0; i < SCHK; i++) {
        int idx = base + i;
        int v = 0;
        if (idx < NN) { v = g_deg[idx]; g_deg[idx] = 0; }
        local[i] = sum;
        sum += v;
    }
    s[t] = sum;
    __syncthreads();
    for (int off = 1; off < 1024; off <<= 1) {
        int v = (t >= off) ? s[t - off] : 0;
        __syncthreads();
        s[t] += v;
        __syncthreads();
    }
    int boff = (t > 0) ? s[t - 1] : 0;
    #pragma unroll
    for (int i = 0; i < SCHK; i++) {
        int idx = base + i;
        if (idx < NN) {
            int r = boff + local[i];
            g_row[idx] = r;
            g_cur[idx] = r;
        }
    }
    if (t == 1023) g_row[NN] = s[1023];
}
__global__ void fill_k(const int* __restrict__ ei) {
    int e = blockIdx.x * blockDim.x + threadIdx.x;
    if (e >= ET) return;
    int s, d;
    if (e < EE) { s = ei[e]; d = ei[EE + e]; } else { s = d = e - EE; }
    int p = atomicAdd(&g_cur[d], 1);
    g_srcs[p] = s;
}

// ---------------- weight transpose+split -------------------------------------
__global__ void transpose_k(const float* __restrict__ W,
                            __nv_bfloat16* __restrict__ whi, __nv_bfloat16* __restrict__ wlo,
                            int M, int K)
{
    __shared__ float t[32][33];
    int x = blockIdx.x * 32 + threadIdx.x;
    int y0 = blockIdx.y * 32;
    for (int i = threadIdx.y; i < 32; i += 8)
        t[i][threadIdx.x] = W[(size_t)(y0 + i) * K + x];
    __syncthreads();
    int xo = y0 + threadIdx.x;
    int yo0 = blockIdx.x * 32;
    for (int i = threadIdx.y; i < 32; i += 8) {
        __nv_bfloat16 h, l;
        split_bf(t[threadIdx.x][i], h, l);
        whi[(size_t)(yo0 + i) * M + xo] = h;
        wlo[(size_t)(yo0 + i) * M + xo] = l;
    }
}

// ---------------- bf16-split GEMM: 128x256 CTA tile, 512 thr, 4-stage --------
#define ATILE 16384
#define BTILE 32768
#define STAGEB (ATILE + BTILE)
#define NSTAGE 4
#define GEMM_SMEM (NSTAGE * STAGEB)   // 192KB

__device__ __forceinline__ uint32_t swoff(int r, int cByte) {
    return (uint32_t)(r * 128 + (cByte ^ ((r & 7) << 4)));
}

__device__ __forceinline__ void issue_copies(
    uint32_t sbase, int buf,
    const __nv_bfloat16* __restrict__ Ahi, const __nv_bfloat16* __restrict__ Alo,
    const __nv_bfloat16* __restrict__ Bhi, const __nv_bfloat16* __restrict__ Blo,
    int NR, int KD, int row0, int col0, int k0, int tid)
{
    uint32_t stg = sbase + buf * STAGEB;
    #pragma unroll
    for (int j = 0; j < 6; j++) {
        int id = tid + j * 512;              // 0..3071
        uint32_t dst;
        const __nv_bfloat16* src;
        int sz = 16;
        if (id < 1024) {                     // A: hi then lo
            int lo = id >> 9;
            int p = id & 511;
            int r = p >> 2, kc = p & 3;
            int gr = row0 + r;
            if (gr >= NR) { gr = NR - 1; sz = 0; }
            dst = stg + swoff(r, (lo ? 64 : 0) + kc * 16);
            src = (lo ? Alo : Ahi) + (size_t)gr * KD + k0 + kc * 8;
        } else {                             // B: hi (1024..2047), lo (2048..3071)
            int lo = (id >= 2048);
            int p = (id - 1024) & 1023;
            int r = p >> 2, kc = p & 3;      // r 0..255
            dst = stg + ATILE + swoff(r, (lo ? 64 : 0) + kc * 16);
            src = (lo ? Blo : Bhi) + (size_t)(col0 + r) * KD + k0 + kc * 8;
        }
        asm volatile("cp.async.cg.shared.global [%0], [%1], 16, %2;"
                     :: "r"(dst), "l"(src), "r"(sz));
    }
}

__global__ __launch_bounds__(512, 1) void gemm_mma_k(
    const __nv_bfloat16* __restrict__ Ahi, const __nv_bfloat16* __restrict__ Alo,
    const __nv_bfloat16* __restrict__ Bhi, const __nv_bfloat16* __restrict__ Blo,
    __half* __restrict__ C, int NR, int KD, int KO,
    const float* __restrict__ a_s, const float* __restrict__ a_d,
    float* __restrict__ ss, float* __restrict__ sd,
    int hstr, int headC)
{
    extern __shared__ char smem[];
    uint32_t sbase = smem_u32(smem);
    const int tid = threadIdx.x;
    const int wid = tid >> 5, lane = tid & 31;
    const int row0 = blockIdx.y * 128, col0 = blockIdx.x * 256;
    const int m0 = (wid >> 3) * 64, n0 = (wid & 7) * 32;   // warp tile 64x32
    const int nc = KD / 32;

    const int arow = (lane & 15);
    const int acb  = ((lane >> 4) & 1) * 16;
    const int brow = (lane & 7) + ((lane >> 4) & 1) * 8;
    const int bcb  = ((lane >> 3) & 1) * 16;

    float d[4][4][4];
    #pragma unroll
    for (int i = 0; i < 4; i++)
        #pragma unroll
        for (int j = 0; j < 4; j++)
            { d[i][j][0] = 0.f; d[i][j][1] = 0.f; d[i][j][2] = 0.f; d[i][j][3] = 0.f; }

    issue_copies(sbase, 0, Ahi, Alo, Bhi, Blo, NR, KD, row0, col0, 0, tid);
    asm volatile("cp.async.commit_group;" ::: "memory");
    issue_copies(sbase, 1, Ahi, Alo, Bhi, Blo, NR, KD, row0, col0, 32, tid);
    asm volatile("cp.async.commit_group;" ::: "memory");
    issue_copies(sbase, 2, Ahi, Alo, Bhi, Blo, NR, KD, row0, col0, 64, tid);
    asm volatile("cp.async.commit_group;" ::: "memory");

    int buf = 0;
    for (int c = 0; c < nc; c++) {
        if (c + 2 < nc)      { asm volatile("cp.async.wait_group 2;" ::: "memory"); }
        else if (c + 1 < nc) { asm volatile("cp.async.wait_group 1;" ::: "memory"); }
        else                 { asm volatile("cp.async.wait_group 0;" ::: "memory"); }
        __syncthreads();

        uint32_t aBase = sbase + buf * STAGEB;
        uint32_t bBase = aBase + ATILE;
        #pragma unroll
        for (int s = 0; s < 2; s++) {
            uint32_t Ah[4][4], Al[4][4], Bh[4][2], Bl[4][2];
            #pragma unroll
            for (int mt = 0; mt < 4; mt++) {
                int r = m0 + mt * 16 + arow;
                LDSM4(Ah[mt][0], Ah[mt][1], Ah[mt][2], Ah[mt][3],
                      aBase + swoff(r, s * 32 + acb));
                LDSM4(Al[mt][0], Al[mt][1], Al[mt][2], Al[mt][3],
                      aBase + swoff(r, 64 + s * 32 + acb));
            }
            #pragma unroll
            for (int p = 0; p < 2; p++) {
                int r = n0 + p * 16 + brow;
                LDSM4(Bh[2 * p][0], Bh[2 * p][1], Bh[2 * p + 1][0], Bh[2 * p + 1][1],
                      bBase + swoff(r, s * 32 + bcb));
                LDSM4(Bl[2 * p][0], Bl[2 * p][1], Bl[2 * p + 1][0], Bl[2 * p + 1][1],
                      bBase + swoff(r, 64 + s * 32 + bcb));
            }
            #pragma unroll
            for (int mt = 0; mt < 4; mt++)
                #pragma unroll
                for (int nt = 0; nt < 4; nt++) {
                    MMA_BF16(d[mt][nt], Ah[mt], Bh[nt]);
                    MMA_BF16(d[mt][nt], Ah[mt], Bl[nt]);
                    MMA_BF16(d[mt][nt], Al[mt], Bh[nt]);
                }
        }

        if (c + 3 < nc) {
            int nb = buf + 3; if (nb >= NSTAGE) nb -= NSTAGE;
            issue_copies(sbase, nb, Ahi, Alo, Bhi, Blo, NR, KD, row0, col0,
                         (c + 3) * 32, tid);
            asm volatile("cp.async.commit_group;" ::: "memory");
        }
        if (++buf == NSTAGE) buf = 0;
    }
    __syncthreads();

    // ---- C store (fp16) ----
    #pragma unroll
    for (int mt = 0; mt < 4; mt++) {
        #pragma unroll
        for (int nt = 0; nt < 4; nt++) {
            int row = row0 + m0 + mt * 16 + (lane >> 2);
            int col = col0 + n0 + nt * 8 + (lane & 3) * 2;
            if (row < NR)
                *(__half2*)(C + (size_t)row * KO + col) =
                    __floats2half2_rn(d[mt][nt][0], d[mt][nt][1]);
            if (row + 8 < NR)
                *(__half2*)(C + (size_t)(row + 8) * KO + col) =
                    __floats2half2_rn(d[mt][nt][2], d[mt][nt][3]);
        }
    }

    // ---- fused attention scores (CTA covers whole heads: pure stores) ------
    // s_sc layout: [seg][ss/sd][128], seg = n-warp's head segment
    float* s_sc = (float*)smem;        // 512 floats
    s_sc[tid] = 0.f;
    __syncthreads();

    const int seg = (headC == 128) ? (n0 >> 7) : 0;
    float ps[4][2] = {}, pd[4][2] = {};
    #pragma unroll
    for (int nt = 0; nt < 4; nt++) {
        int cix = col0 + n0 + nt * 8 + (lane & 3) * 2;
        float a0s = a_s[cix], a1s = a_s[cix + 1];
        float a0d = a_d[cix], a1d = a_d[cix + 1];
        #pragma unroll
        for (int mt = 0; mt < 4; mt++) {
            ps[mt][0] += d[mt][nt][0] * a0s + d[mt][nt][1] * a1s;
            ps[mt][1] += d[mt][nt][2] * a0s + d[mt][nt][3] * a1s;
            pd[mt][0] += d[mt][nt][0] * a0d + d[mt][nt][1] * a1d;
            pd[mt][1] += d[mt][nt][2] * a0d + d[mt][nt][3] * a1d;
        }
    }
    #pragma unroll
    for (int mt = 0; mt < 4; mt++)
        #pragma unroll
        for (int rr = 0; rr < 2; rr++) {
            ps[mt][rr] += __shfl_xor_sync(0xffffffffu, ps[mt][rr], 1);
            ps[mt][rr] += __shfl_xor_sync(0xffffffffu, ps[mt][rr], 2);
            pd[mt][rr] += __shfl_xor_sync(0xffffffffu, pd[mt][rr], 1);
            pd[mt][rr] += __shfl_xor_sync(0xffffffffu, pd[mt][rr], 2);
        }
    if ((lane & 3) == 0) {
        int q = lane >> 2;
        #pragma unroll
        for (int mt = 0; mt < 4; mt++)
            #pragma unroll
            for (int rr = 0; rr < 2; rr++) {
                int r = m0 + mt * 16 + rr * 8 + q;
                atomicAdd(&s_sc[seg * 256 + r], ps[mt][rr]);
                atomicAdd(&s_sc[seg * 256 + 128 + r], pd[mt][rr]);
            }
    }
    __syncthreads();
    {
        int segc = tid >> 7;               // 0..3 (seg*2 + ss/sd over 512 threads)
        int r = tid & 127;
        int sseg = segc >> 1, isSd = segc & 1;
        if (sseg * headC < 256) {          // valid segment
            int gr = row0 + r;
            if (gr < NR) {
                int head = col0 / headC + sseg;
                float v = s_sc[sseg * 256 + isSd * 128 + r];
                if (isSd) sd[gr * hstr + head] = v;
                else      ss[gr * hstr + head] = v;
            }
        }
    }
}

// ---------------- CSR aggregation --------------------------------------------
__global__ void agg_k(const __half* __restrict__ hmat,
                      const float* __restrict__ ss, const float* __restrict__ sd,
                      const float* __restrict__ bias,
                      float* __restrict__ outF, __half* __restrict__ outH,
                      int heads, int C, int applyLrelu)
{
    __shared__ float s_p[SMAX * NHEADS];
    __shared__ int   s_src[SMAX];
    __shared__ float s_mx[NHEADS], s_den[NHEADS];

    int n = blockIdx.x;
    int tid = threadIdx.x;
    int row0 = g_row[n];
    int deg = g_row[n + 1] - row0;

    int degc = deg < SMAX ? deg : SMAX;
    for (int i = tid; i < degc; i += blockDim.x) s_src[i] = g_srcs[row0 + i];
    __syncthreads();

    int w = tid >> 5, lane = tid & 31;
    if (w < heads) {
        float sdv = sd[n * heads + w];
        float mx = -3.4e38f;
        for (int i = lane; i < deg; i += 32) {
            int s = (i < SMAX) ? s_src[i] : g_srcs[row0 + i];
            float e = lrelu(ss[s * heads + w] + sdv);
            if (i < SMAX) s_p[i * heads + w] = e;
            mx = fmaxf(mx, e);
        }
        #pragma unroll
        for (int o = 16; o; o >>= 1) mx = fmaxf(mx, __shfl_xor_sync(0xffffffffu, mx, o));
        float den = 0.f;
        for (int i = lane; i < deg; i += 32) {
            float e = (i < SMAX) ? s_p[i * heads + w]
                                 : lrelu(ss[g_srcs[row0 + i] * heads + w] + sdv);
            float p = __expf(e - mx);
            if (i < SMAX) s_p[i * heads + w] = p;
            den += p;
        }
        #pragma unroll
        for (int o = 16; o; o >>= 1) den += __shfl_xor_sync(0xffffffffu, den, o);
        if (lane == 0) { s_mx[w] = mx; s_den[w] = den; }
    }
    __syncthreads();

    int cpq = C >> 2;
    int h = tid / cpq;
    int cq = tid - h * cpq;
    float inv = 1.f / (s_den[h] + 1e-16f);
    float4 acc = make_float4(0.f, 0.f, 0.f, 0.f);

    const size_t hstr = (size_t)heads * C;
    const int coff = h * C + cq * 4;

    if (deg <= SMAX) {
        int i = 0;
        for (; i + 8 <= deg; i += 8) {
            int sx[8]; float px[8]; uint2 rx[8];
            #pragma unroll
            for (int u = 0; u < 8; u++) { sx[u] = s_src[i + u]; px[u] = s_p[(i + u) * heads + h]; }
            #pragma unroll
            for (int u = 0; u < 8; u++)
                rx[u] = *(const uint2*)(hmat + (size_t)sx[u] * hstr + coff);
            #pragma unroll
            for (int u = 0; u < 8; u++) {
                float2 f0 = __half22float2(*reinterpret_cast<__half2*>(&rx[u].x));
                float2 f1 = __half22float2(*reinterpret_cast<__half2*>(&rx[u].y));
                acc.x += f0.x * px[u]; acc.y += f0.y * px[u];
                acc.z += f1.x * px[u]; acc.w += f1.y * px[u];
            }
        }
        for (; i < deg; i++) {
            int s = s_src[i];
            float p = s_p[i * heads + h];
            uint2 r = *(const uint2*)(hmat + (size_t)s * hstr + coff);
            float2 f0 = __half22float2(*reinterpret_cast<__half2*>(&r.x));
            float2 f1 = __half22float2(*reinterpret_cast<__half2*>(&r.y));
            acc.x += f0.x * p; acc.y += f0.y * p; acc.z += f1.x * p; acc.w += f1.y * p;
        }
    } else {
        float mx = s_mx[h];
        float sdv = sd[n * heads + h];
        for (int i = 0; i < deg; i++) {
            int s = (i < SMAX) ? s_src[i] : g_srcs[row0 + i];
            float p = (i < SMAX) ? s_p[i * heads + h]
                                 : __expf(lrelu(ss[s * heads + h] + sdv) - mx);
            uint2 r = *(const uint2*)(hmat + (size_t)s * hstr + coff);
            float2 f0 = __half22float2(*reinterpret_cast<__half2*>(&r.x));
            float2 f1 = __half22float2(*reinterpret_cast<__half2*>(&r.y));
            acc.x += f0.x * p; acc.y += f0.y * p; acc.z += f1.x * p; acc.w += f1.y * p;
        }
    }

    acc.x *= inv; acc.y *= inv; acc.z *= inv; acc.w *= inv;
    int j = h * C + cq * 4;
    float4 bb = *(const float4*)(bias + j);
    acc.x += bb.x; acc.y += bb.y; acc.z += bb.z; acc.w += bb.w;
    if (applyLrelu) {
        acc.x = lrelu(acc.x); acc.y = lrelu(acc.y);
        acc.z = lrelu(acc.z); acc.w = lrelu(acc.w);
    }
    size_t oix = (size_t)n * heads * C + j;
    if (outH) {
        __half2 p0 = __floats2half2_rn(acc.x, acc.y);
        __half2 p1 = __floats2half2_rn(acc.z, acc.w);
        uint2 pk = make_uint2(*reinterpret_cast<uint32_t*>(&p0),
                              *reinterpret_cast<uint32_t*>(&p1));
        *(uint2*)(outH + oix) = pk;
    } else {
        *(float4*)(outF + oix) = acc;
    }
}

// ---------------- batchnorm (fp16 input) -------------------------------------
__global__ void bn_stats_k(const __half* __restrict__ x, float* __restrict__ bn)
{
    int t = threadIdx.x;
    float s0 = 0.f, s1 = 0.f, q0 = 0.f, q1 = 0.f;
    for (int n = blockIdx.x; n < NN; n += gridDim.x) {
        float2 f = __half22float2(*(const __half2*)(x + (size_t)n * H1D + 2 * t));
        s0 += f.x; q0 += f.x * f.x;
        s1 += f.y; q1 += f.y * f.y;
    }
    atomicAdd(bn + 2 * t, s0);       atomicAdd(bn + 2 * t + 1, s1);
    atomicAdd(bn + 512 + 2 * t, q0); atomicAdd(bn + 512 + 2 * t + 1, q1);
}

__global__ void bn_apply_k(const __half* __restrict__ x, const float* __restrict__ bn,
                           const float* __restrict__ gamma, const float* __restrict__ beta,
                           __nv_bfloat16* __restrict__ hi, __nv_bfloat16* __restrict__ lo)
{
    int i = blockIdx.x * blockDim.x + threadIdx.x;
    if (i >= NN * H1D / 2) return;
    int c = (2 * i) & 511;
    const float invN = 1.0f / NN;
    float2 f = __half22float2(*(const __half2*)(x + (size_t)2 * i));
    float mu0 = bn[c] * invN, mu1 = bn[c + 1] * invN;
    float va0 = bn[512 + c] * invN - mu0 * mu0;
    float va1 = bn[512 + c + 1] * invN - mu1 * mu1;
    float v0 = lrelu(gamma[c] * (f.x - mu0) * rsqrtf(va0 + 1e-5f) + beta[c]);
    float v1 = lrelu(gamma[c + 1] * (f.y - mu1) * rsqrtf(va1 + 1e-5f) + beta[c + 1]);
    __nv_bfloat16 h0, l0, h1, l1;
    split_bf(v0, h0, l0); split_bf(v1, h1, l1);
    __nv_bfloat162 hh; hh.x = h0; hh.y = h1;
    __nv_bfloat162 ll; ll.x = l0; ll.y = l1;
    *(__nv_bfloat162*)(hi + (size_t)2 * i) = hh;
    *(__nv_bfloat162*)(lo + (size_t)2 * i) = ll;
}

// ---------------- pooling ----------------------------------------------------
#define PCH 8
__global__ void pool_acc_k(const float* __restrict__ h3, const int* __restrict__ batch,
                           float* __restrict__ out, float* __restrict__ cnt)
{
    int c = threadIdx.x;
    int n0 = blockIdx.x * PCH;
    if (n0 >= NN) return;
    float acc = 0.f, ac = 0.f;
    int curb = batch[n0];
    #pragma unroll
    for (int k = 0; k < PCH; k++) {
        int n = n0 + k;
        if (n >= NN) break;
        int b = batch[n];
        if (b != curb) {
            atomicAdd(out + curb * OUTD + c, acc);
            if (c == 0) atomicAdd(cnt + curb, ac);
            acc = 0.f; ac = 0.f; curb = b;
        }
        acc += h3[(size_t)n * OUTD + c];
        ac += 1.f;
    }
    atomicAdd(out + curb * OUTD + c, acc);
    if (c == 0) atomicAdd(cnt + curb, ac);
}
__global__ void pool_div_k(float* __restrict__ out, const float* __restrict__ cnt)
{
    int i = blockIdx.x * blockDim.x + threadIdx.x;
    if (i >= BB * OUTD) return;
    float c = cnt[i >> 8];
    out[i] /= (c > 1.f ? c : 1.f);
}

// ---------------- host orchestration ----------------------------------------
static inline int ceil_div(int a, int b) { return (a + b - 1) / b; }

extern "C" void kernel_launch(void* const* d_in, const int* in_sizes, int n_in,
                              void* d_out, int out_size)
{
    const float* x      = (const float*)d_in[0];
    const int*   ei     = (const int*)  d_in[1];
    const int*   batch  = (const int*)  d_in[2];
    const float* W1     = (const float*)d_in[3];
    const float* asrc1  = (const float*)d_in[4];
    const float* adst1  = (const float*)d_in[5];
    const float* b1     = (const float*)d_in[6];
    const float* gamma1 = (const float*)d_in[7];
    const float* beta1  = (const float*)d_in[8];
    const float* W2     = (const float*)d_in[9];
    const float* asrc2  = (const float*)d_in[10];
    const float* adst2  = (const float*)d_in[11];
    const float* b2     = (const float*)d_in[12];
    const float* gamma2 = (const float*)d_in[13];
    const float* beta2  = (const float*)d_in[14];
    const float* W3     = (const float*)d_in[15];
    const float* asrc3  = (const float*)d_in[16];
    const float* adst3  = (const float*)d_in[17];
    const float* b3     = (const float*)d_in[18];
    float* out = (float*)d_out;

    float *featB, *ssB, *sdB, *bnB, *cntB;
    __half *hB, *fhB;
    __nv_bfloat16 *ahiB, *aloB, *whiB, *wloB;
    cudaGetSymbolAddress((void**)&hB,    g_h);
    cudaGetSymbolAddress((void**)&fhB,   g_fh);
    cudaGetSymbolAddress((void**)&featB, g_feat);
    cudaGetSymbolAddress((void**)&ahiB,  g_ahi);
    cudaGetSymbolAddress((void**)&aloB,  g_alo);
    cudaGetSymbolAddress((void**)&whiB,  g_whi);
    cudaGetSymbolAddress((void**)&wloB,  g_wlo);
    cudaGetSymbolAddress((void**)&ssB,   g_ssrc);
    cudaGetSymbolAddress((void**)&sdB,   g_sdst);
    cudaGetSymbolAddress((void**)&bnB,   g_bn);
    cudaGetSymbolAddress((void**)&cntB,  g_cnt);

    cudaFuncSetAttribute(gemm_mma_k, cudaFuncAttributeMaxDynamicSharedMemorySize, GEMM_SMEM);

    int rowBlocks = ceil_div(NN, 128);

    prep1_k<<<T1BLK + SPLBLK, dim3(32, 8)>>>(W1, whiB, wloB, x, ahiB, aloB);
    deg_k <<<ceil_div(ET, 256), 256>>>(ei);
    scan_k<<<1, 1024>>>();

    // ================= Layer 1 (gemm = 4th kernel: ncu target) =============
    gemm_mma_k<<<dim3(H1D / 256, rowBlocks), 512, GEMM_SMEM>>>(
        ahiB, aloB, whiB, wloB, hB, NN, IND, H1D, asrc1, adst1, ssB, sdB, NHEADS, 128);
    fill_k<<<ceil_div(ET, 256), 256>>>(ei);
    agg_k<<<NN, NHEADS * (HIDC / 4)>>>(hB, ssB, sdB, b1, nullptr, fhB, NHEADS, HIDC, 0);
    cudaMemsetAsync(bnB, 0, 2 * H1D * sizeof(float));
    bn_stats_k<<<592, 256>>>(fhB, bnB);
    bn_apply_k<<<ceil_div(NN * H1D / 2, 256), 256>>>(fhB, bnB, gamma1, beta1, ahiB, aloB);

    // ================= Layer 2 =================
    transpose_k<<<dim3(H1D / 32, H1D / 32), dim3(32, 8)>>>(W2, whiB, wloB, H1D, H1D);
    gemm_mma_k<<<dim3(H1D / 256, rowBlocks), 512, GEMM_SMEM>>>(
        ahiB, aloB, whiB, wloB, hB, NN, H1D, H1D, asrc2, adst2, ssB, sdB, NHEADS, 128);
    agg_k<<<NN, NHEADS * (HIDC / 4)>>>(hB, ssB, sdB, b2, nullptr, fhB, NHEADS, HIDC, 0);
    cudaMemsetAsync(bnB, 0, 2 * H1D * sizeof(float));
    bn_stats_k<<<592, 256>>>(fhB, bnB);
    bn_apply_k<<<ceil_div(NN * H1D / 2, 256), 256>>>(fhB, bnB, gamma2, beta2, ahiB, aloB);

    // ================= Layer 3 =================
    transpose_k<<<dim3(OUTD / 32, H1D / 32), dim3(32, 8)>>>(W3, whiB, wloB, H1D, OUTD);
    gemm_mma_k<<<dim3(OUTD / 256, rowBlocks), 512, GEMM_SMEM>>>(
        ahiB, aloB, whiB, wloB, hB, NN, H1D, OUTD, asrc3, adst3, ssB, sdB, 1, 256);
    agg_k<<<NN, OUTD / 4>>>(hB, ssB, sdB, b3, featB, nullptr, 1, OUTD, 1);

    // ================= Global mean pool =================
    cudaMemsetAsync(out, 0, (size_t)BB * OUTD * sizeof(float));
    cudaMemsetAsync(cntB, 0, BB * sizeof(float));
    pool_acc_k<<<ceil_div(NN, PCH), OUTD>>>(featB, batch, out, cntB);
    pool_div_k<<<ceil_div(BB * OUTD, 256), 256>>>(out, cntB);
}

// round 17
// speedup vs baseline: 1.1166x; 1.1166x over previous
#include <cuda_runtime.h>
#include <cuda_fp16.h>
#include <cuda_bf16.h>
#include <cstdint>
#include <cstddef>

#define NN    20000
#define EE    320000
#define ET    340000
#define BB    64
#define IND   768
#define H1D   512
#define NHEADS 4
#define HIDC  128
#define OUTD  256
#define SMAX  192

// ---------------- scratch (device globals) ----------------------------------
__device__ __half g_h  [(size_t)NN * H1D];
__device__ __half g_fh [(size_t)NN * H1D];
__device__ float g_feat[(size_t)NN * OUTD];
__device__ __nv_bfloat16 g_ahi[(size_t)NN * IND];
__device__ __nv_bfloat16 g_alo[(size_t)NN * IND];
__device__ __nv_bfloat16 g_whi [(size_t)IND * H1D];   // W1^T
__device__ __nv_bfloat16 g_wlo [(size_t)IND * H1D];
__device__ __nv_bfloat16 g_whi2[(size_t)H1D * H1D];   // W2^T
__device__ __nv_bfloat16 g_wlo2[(size_t)H1D * H1D];
__device__ __nv_bfloat16 g_whi3[(size_t)H1D * OUTD];  // W3^T
__device__ __nv_bfloat16 g_wlo3[(size_t)H1D * OUTD];
__device__ float g_ssrc[NN * NHEADS];
__device__ float g_sdst[NN * NHEADS];
__device__ float g_bn  [2 * H1D];
__device__ float g_cnt [BB];
__device__ int   g_deg [NN];
__device__ int   g_row [NN + 1];
__device__ int   g_cur [NN];
__device__ int   g_srcs[ET];

__device__ __forceinline__ float lrelu(float v) { return v > 0.f ? v : 0.2f * v; }

__device__ __forceinline__ void split_bf(float v, __nv_bfloat16& h, __nv_bfloat16& l) {
    h = __float2bfloat16(v);
    l = __float2bfloat16(v - __bfloat162float(h));
}

#define LDSM4(r0, r1, r2, r3, addr) \
    asm volatile("ldmatrix.sync.aligned.m8n8.x4.shared.b16 {%0,%1,%2,%3}, [%4];" \
        : "=r"(r0), "=r"(r1), "=r"(r2), "=r"(r3) : "r"(addr))

#define MMA_BF16(d, a, b) \
    asm volatile("mma.sync.aligned.m16n8k16.row.col.f32.bf16.bf16.f32 " \
        "{%0,%1,%2,%3}, {%4,%5,%6,%7}, {%8,%9}, {%0,%1,%2,%3};" \
        : "+f"((d)[0]), "+f"((d)[1]), "+f"((d)[2]), "+f"((d)[3]) \
        : "r"((a)[0]), "r"((a)[1]), "r"((a)[2]), "r"((a)[3]), "r"((b)[0]), "r"((b)[1]))

__device__ __forceinline__ uint32_t smem_u32(const void* p) {
    uint32_t a;
    asm("{ .reg .u64 t; cvta.to.shared.u64 t, %1; cvt.u32.u64 %0, t; }" : "=r"(a) : "l"(p));
    return a;
}

// ---------------- prep1: ALL weight transposes + x split ---------------------
// W[M,K] -> WT hi/lo [K][M]
__device__ __forceinline__ void tr_block(
    const float* __restrict__ W, __nv_bfloat16* __restrict__ whi,
    __nv_bfloat16* __restrict__ wlo, int M, int K, int bx, int by,
    int tx, int ty, float (*t)[33])
{
    int xcol = bx * 32 + tx;
    int y0 = by * 32;
    for (int i = ty; i < 32; i += 8)
        t[i][tx] = W[(size_t)(y0 + i) * K + xcol];
    __syncthreads();
    int xo = y0 + tx;
    int yo0 = bx * 32;
    for (int i = ty; i < 32; i += 8) {
        __nv_bfloat16 h, l;
        split_bf(t[tx][i], h, l);
        whi[(size_t)(yo0 + i) * M + xo] = h;
        wlo[(size_t)(yo0 + i) * M + xo] = l;
    }
}

#define T1BLK ((H1D / 32) * (IND / 32))     // 384
#define T2BLK ((H1D / 32) * (H1D / 32))     // 256
#define T3BLK ((OUTD / 32) * (H1D / 32))    // 128
#define TALL  (T1BLK + T2BLK + T3BLK)       // 768
#define SPLBLK ((NN * IND / 4 + 255) / 256)
__global__ void prep1_k(const float* __restrict__ W1,
                        __nv_bfloat16* __restrict__ whi1, __nv_bfloat16* __restrict__ wlo1,
                        const float* __restrict__ W2,
                        __nv_bfloat16* __restrict__ whi2, __nv_bfloat16* __restrict__ wlo2,
                        const float* __restrict__ W3,
                        __nv_bfloat16* __restrict__ whi3, __nv_bfloat16* __restrict__ wlo3,
                        const float* __restrict__ x,
                        __nv_bfloat16* __restrict__ ahi, __nv_bfloat16* __restrict__ alo)
{
    __shared__ float t[32][33];
    int bid = blockIdx.x;
    int tx = threadIdx.x, ty = threadIdx.y;
    if (bid < T1BLK) {
        tr_block(W1, whi1, wlo1, IND, H1D, bid % (H1D / 32), bid / (H1D / 32), tx, ty, t);
    } else if (bid < T1BLK + T2BLK) {
        int lb = bid - T1BLK;
        tr_block(W2, whi2, wlo2, H1D, H1D, lb % (H1D / 32), lb / (H1D / 32), tx, ty, t);
    } else if (bid < TALL) {
        int lb = bid - T1BLK - T2BLK;
        tr_block(W3, whi3, wlo3, H1D, OUTD, lb % (OUTD / 32), lb / (OUTD / 32), tx, ty, t);
    } else {
        int i = ((bid - TALL) * 256 + ty * 32 + tx) * 4;
        if (i < NN * IND) {
            float4 v = *(const float4*)(x + i);
            __nv_bfloat16 h0, l0, h1, l1, h2, l2, h3, l3;
            split_bf(v.x, h0, l0); split_bf(v.y, h1, l1);
            split_bf(v.z, h2, l2); split_bf(v.w, h3, l3);
            ahi[i] = h0; ahi[i + 1] = h1; ahi[i + 2] = h2; ahi[i + 3] = h3;
            alo[i] = l0; alo[i + 1] = l1; alo[i + 2] = l2; alo[i + 3] = l3;
        }
    }
}

// ---------------- CSR build --------------------------------------------------
__global__ void deg_k(const int* __restrict__ ei) {
    int e = blockIdx.x * blockDim.x + threadIdx.x;
    if (e >= ET) return;
    int d = (e < EE) ? ei[EE + e] : (e - EE);
    atomicAdd(&g_deg[d], 1);
}
#define SCHK 20
__global__ __launch_bounds__(1024) void scan_k() {
    __shared__ int s[1024];
    int t = threadIdx.x;
    int base = t * SCHK;
    int local[SCHK];
    int sum = 0;
    #pragma unroll
    for (int i = 0; i < SCHK; i++) {
        int idx = base + i;
        int v = 0;
        if (idx < NN) { v = g_deg[idx]; g_deg[idx] = 0; }
        local[i] = sum;
        sum += v;
    }
    s[t] = sum;
    __syncthreads();
    for (int off = 1; off < 1024; off <<= 1) {
        int v = (t >= off) ? s[t - off] : 0;
        __syncthreads();
        s[t] += v;
        __syncthreads();
    }
    int boff = (t > 0) ? s[t - 1] : 0;
    #pragma unroll
    for (int i = 0; i < SCHK; i++) {
        int idx = base + i;
        if (idx < NN) {
            int r = boff + local[i];
            g_row[idx] = r;
            g_cur[idx] = r;
        }
    }
    if (t == 1023) g_row[NN] = s[1023];
}
__global__ void fill_k(const int* __restrict__ ei) {
    int e = blockIdx.x * blockDim.x + threadIdx.x;
    if (e >= ET) return;
    int s, d;
    if (e < EE) { s = ei[e]; d = ei[EE + e]; } else { s = d = e - EE; }
    int p = atomicAdd(&g_cur[d], 1);
    g_srcs[p] = s;
}

// ---------------- bf16-split GEMM: 256 thr, 64x32 warp tile, 3-stage ---------
#define TILEB 16384
#define NSTAGE 3
#define GEMM_SMEM (2 * NSTAGE * TILEB)   // 96KB

__device__ __forceinline__ uint32_t swoff(int r, int cByte) {
    return (uint32_t)(r * 128 + (cByte ^ ((r & 7) << 4)));
}

__device__ __forceinline__ void issue_copies(
    uint32_t sA, uint32_t sB, int buf,
    const __nv_bfloat16* __restrict__ Ahi, const __nv_bfloat16* __restrict__ Alo,
    const __nv_bfloat16* __restrict__ Bhi, const __nv_bfloat16* __restrict__ Blo,
    int NR, int KD, int row0, int col0, int k0, int tid)
{
    #pragma unroll
    for (int j = 0; j < 8; j++) {
        int id = tid + j * 256;
        int plane = id >> 9;
        int p = id & 511;
        int r = p >> 2, kc = p & 3;
        uint32_t dst;
        const __nv_bfloat16* src;
        int sz = 16;
        if (plane < 2) {
            int gr = row0 + r;
            if (gr >= NR) { gr = NR - 1; sz = 0; }
            dst = sA + buf * TILEB + swoff(r, (plane ? 64 : 0) + kc * 16);
            src = (plane ? Alo : Ahi) + (size_t)gr * KD + k0 + kc * 8;
        } else {
            dst = sB + buf * TILEB + swoff(r, ((plane & 1) ? 64 : 0) + kc * 16);
            src = ((plane & 1) ? Blo : Bhi) + (size_t)(col0 + r) * KD + k0 + kc * 8;
        }
        asm volatile("cp.async.cg.shared.global [%0], [%1], 16, %2;"
                     :: "r"(dst), "l"(src), "r"(sz));
    }
}

__global__ __launch_bounds__(256, 2) void gemm_mma_k(
    const __nv_bfloat16* __restrict__ Ahi, const __nv_bfloat16* __restrict__ Alo,
    const __nv_bfloat16* __restrict__ Bhi, const __nv_bfloat16* __restrict__ Blo,
    __half* __restrict__ C, int NR, int KD, int KO,
    const float* __restrict__ a_s, const float* __restrict__ a_d,
    float* __restrict__ ss, float* __restrict__ sd,
    int hstr, int headC)
{
    extern __shared__ char smem[];
    uint32_t sA = smem_u32(smem);
    uint32_t sB = sA + NSTAGE * TILEB;
    const int tid = threadIdx.x;
    const int wid = tid >> 5, lane = tid & 31;
    const int row0 = blockIdx.y * 128, col0 = blockIdx.x * 128;
    const int m0 = (wid >> 2) * 64, n0 = (wid & 3) * 32;
    const int nc = KD / 32;

    const int arow = (lane & 15);
    const int acb  = ((lane >> 4) & 1) * 16;
    const int brow = (lane & 7) + ((lane >> 4) & 1) * 8;
    const int bcb  = ((lane >> 3) & 1) * 16;

    float d[4][4][4];
    #pragma unroll
    for (int i = 0; i < 4; i++)
        #pragma unroll
        for (int j = 0; j < 4; j++)
            { d[i][j][0] = 0.f; d[i][j][1] = 0.f; d[i][j][2] = 0.f; d[i][j][3] = 0.f; }

    issue_copies(sA, sB, 0, Ahi, Alo, Bhi, Blo, NR, KD, row0, col0, 0, tid);
    asm volatile("cp.async.commit_group;" ::: "memory");
    issue_copies(sA, sB, 1, Ahi, Alo, Bhi, Blo, NR, KD, row0, col0, 32, tid);
    asm volatile("cp.async.commit_group;" ::: "memory");

    int buf = 0;
    for (int c = 0; c < nc; c++) {
        if (c < nc - 1) { asm volatile("cp.async.wait_group 1;" ::: "memory"); }
        else            { asm volatile("cp.async.wait_group 0;" ::: "memory"); }
        __syncthreads();

        uint32_t aBase = sA + buf * TILEB;
        uint32_t bBase = sB + buf * TILEB;
        #pragma unroll
        for (int s = 0; s < 2; s++) {
            uint32_t Ah[4][4], Al[4][4], Bh[4][2], Bl[4][2];
            #pragma unroll
            for (int mt = 0; mt < 4; mt++) {
                int r = m0 + mt * 16 + arow;
                LDSM4(Ah[mt][0], Ah[mt][1], Ah[mt][2], Ah[mt][3],
                      aBase + swoff(r, s * 32 + acb));
                LDSM4(Al[mt][0], Al[mt][1], Al[mt][2], Al[mt][3],
                      aBase + swoff(r, 64 + s * 32 + acb));
            }
            #pragma unroll
            for (int p = 0; p < 2; p++) {
                int r = n0 + p * 16 + brow;
                LDSM4(Bh[2 * p][0], Bh[2 * p][1], Bh[2 * p + 1][0], Bh[2 * p + 1][1],
                      bBase + swoff(r, s * 32 + bcb));
                LDSM4(Bl[2 * p][0], Bl[2 * p][1], Bl[2 * p + 1][0], Bl[2 * p + 1][1],
                      bBase + swoff(r, 64 + s * 32 + bcb));
            }
            #pragma unroll
            for (int mt = 0; mt < 4; mt++)
                #pragma unroll
                for (int nt = 0; nt < 4; nt++) {
                    MMA_BF16(d[mt][nt], Ah[mt], Bh[nt]);
                    MMA_BF16(d[mt][nt], Ah[mt], Bl[nt]);
                    MMA_BF16(d[mt][nt], Al[mt], Bh[nt]);
                }
        }

        if (c + 2 < nc) {
            int nb = buf + 2; if (nb >= NSTAGE) nb -= NSTAGE;
            issue_copies(sA, sB, nb, Ahi, Alo, Bhi, Blo, NR, KD, row0, col0,
                         (c + 2) * 32, tid);
            asm volatile("cp.async.commit_group;" ::: "memory");
        }
        if (++buf == NSTAGE) buf = 0;
    }
    __syncthreads();

    // ---- C store (fp16) ----
    #pragma unroll
    for (int mt = 0; mt < 4; mt++) {
        #pragma unroll
        for (int nt = 0; nt < 4; nt++) {
            int row = row0 + m0 + mt * 16 + (lane >> 2);
            int col = col0 + n0 + nt * 8 + (lane & 3) * 2;
            if (row < NR)
                *(__half2*)(C + (size_t)row * KO + col) =
                    __floats2half2_rn(d[mt][nt][0], d[mt][nt][1]);
            if (row + 8 < NR)
                *(__half2*)(C + (size_t)(row + 8) * KO + col) =
                    __floats2half2_rn(d[mt][nt][2], d[mt][nt][3]);
        }
    }

    // ---- fused attention scores ----
    float* s_sc = (float*)smem;
    if (tid < 256) s_sc[tid] = 0.f;
    __syncthreads();

    float ps[4][2] = {}, pd[4][2] = {};
    #pragma unroll
    for (int nt = 0; nt < 4; nt++) {
        int cix = col0 + n0 + nt * 8 + (lane & 3) * 2;
        float a0s = a_s[cix], a1s = a_s[cix + 1];
        float a0d = a_d[cix], a1d = a_d[cix + 1];
        #pragma unroll
        for (int mt = 0; mt < 4; mt++) {
            ps[mt][0] += d[mt][nt][0] * a0s + d[mt][nt][1] * a1s;
            ps[mt][1] += d[mt][nt][2] * a0s + d[mt][nt][3] * a1s;
            pd[mt][0] += d[mt][nt][0] * a0d + d[mt][nt][1] * a1d;
            pd[mt][1] += d[mt][nt][2] * a0d + d[mt][nt][3] * a1d;
        }
    }
    #pragma unroll
    for (int mt = 0; mt < 4; mt++)
        #pragma unroll
        for (int rr = 0; rr < 2; rr++) {
            ps[mt][rr] += __shfl_xor_sync(0xffffffffu, ps[mt][rr], 1);
            ps[mt][rr] += __shfl_xor_sync(0xffffffffu, ps[mt][rr], 2);
            pd[mt][rr] += __shfl_xor_sync(0xffffffffu, pd[mt][rr], 1);
            pd[mt][rr] += __shfl_xor_sync(0xffffffffu, pd[mt][rr], 2);
        }
    if ((lane & 3) == 0) {
        int q = lane >> 2;
        #pragma unroll
        for (int mt = 0; mt < 4; mt++)
            #pragma unroll
            for (int rr = 0; rr < 2; rr++) {
                int r = m0 + mt * 16 + rr * 8 + q;
                atomicAdd(&s_sc[r], ps[mt][rr]);
                atomicAdd(&s_sc[128 + r], pd[mt][rr]);
            }
    }
    __syncthreads();
    if (tid < 128) {
        int gr = row0 + tid;
        if (gr < NR) {
            int head = col0 / headC;
            if (headC == 128) {
                ss[gr * hstr + head] = s_sc[tid];
                sd[gr * hstr + head] = s_sc[128 + tid];
            } else {
                atomicAdd(&ss[gr * hstr + head], s_sc[tid]);
                atomicAdd(&sd[gr * hstr + head], s_sc[128 + tid]);
            }
        }
    }
}

// ---------------- CSR aggregation --------------------------------------------
__global__ void agg_k(const __half* __restrict__ hmat,
                      const float* __restrict__ ss, const float* __restrict__ sd,
                      const float* __restrict__ bias,
                      float* __restrict__ outF, __half* __restrict__ outH,
                      int heads, int C, int applyLrelu)
{
    __shared__ float s_p[SMAX * NHEADS];
    __shared__ int   s_src[SMAX];
    __shared__ float s_mx[NHEADS], s_den[NHEADS];

    int n = blockIdx.x;
    int tid = threadIdx.x;
    int row0 = g_row[n];
    int deg = g_row[n + 1] - row0;

    int degc = deg < SMAX ? deg : SMAX;
    for (int i = tid; i < degc; i += blockDim.x) s_src[i] = g_srcs[row0 + i];
    __syncthreads();

    int w = tid >> 5, lane = tid & 31;
    if (w < heads) {
        float sdv = sd[n * heads + w];
        float mx = -3.4e38f;
        for (int i = lane; i < deg; i += 32) {
            int s = (i < SMAX) ? s_src[i] : g_srcs[row0 + i];
            float e = lrelu(ss[s * heads + w] + sdv);
            if (i < SMAX) s_p[i * heads + w] = e;
            mx = fmaxf(mx, e);
        }
        #pragma unroll
        for (int o = 16; o; o >>= 1) mx = fmaxf(mx, __shfl_xor_sync(0xffffffffu, mx, o));
        float den = 0.f;
        for (int i = lane; i < deg; i += 32) {
            float e = (i < SMAX) ? s_p[i * heads + w]
                                 : lrelu(ss[g_srcs[row0 + i] * heads + w] + sdv);
            float p = __expf(e - mx);
            if (i < SMAX) s_p[i * heads + w] = p;
            den += p;
        }
        #pragma unroll
        for (int o = 16; o; o >>= 1) den += __shfl_xor_sync(0xffffffffu, den, o);
        if (lane == 0) { s_mx[w] = mx; s_den[w] = den; }
    }
    __syncthreads();

    int cpq = C >> 2;
    int h = tid / cpq;
    int cq = tid - h * cpq;
    float inv = 1.f / (s_den[h] + 1e-16f);
    float4 acc = make_float4(0.f, 0.f, 0.f, 0.f);

    const size_t hstr = (size_t)heads * C;
    const int coff = h * C + cq * 4;

    if (deg <= SMAX) {
        int i = 0;
        for (; i + 8 <= deg; i += 8) {
            int sx[8]; float px[8]; uint2 rx[8];
            #pragma unroll
            for (int u = 0; u < 8; u++) { sx[u] = s_src[i + u]; px[u] = s_p[(i + u) * heads + h]; }
            #pragma unroll
            for (int u = 0; u < 8; u++)
                rx[u] = *(const uint2*)(hmat + (size_t)sx[u] * hstr + coff);
            #pragma unroll
            for (int u = 0; u < 8; u++) {
                float2 f0 = __half22float2(*reinterpret_cast<__half2*>(&rx[u].x));
                float2 f1 = __half22float2(*reinterpret_cast<__half2*>(&rx[u].y));
                acc.x += f0.x * px[u]; acc.y += f0.y * px[u];
                acc.z += f1.x * px[u]; acc.w += f1.y * px[u];
            }
        }
        for (; i < deg; i++) {
            int s = s_src[i];
            float p = s_p[i * heads + h];
            uint2 r = *(const uint2*)(hmat + (size_t)s * hstr + coff);
            float2 f0 = __half22float2(*reinterpret_cast<__half2*>(&r.x));
            float2 f1 = __half22float2(*reinterpret_cast<__half2*>(&r.y));
            acc.x += f0.x * p; acc.y += f0.y * p; acc.z += f1.x * p; acc.w += f1.y * p;
        }
    } else {
        float mx = s_mx[h];
        float sdv = sd[n * heads + h];
        for (int i = 0; i < deg; i++) {
            int s = (i < SMAX) ? s_src[i] : g_srcs[row0 + i];
            float p = (i < SMAX) ? s_p[i * heads + h]
                                 : __expf(lrelu(ss[s * heads + h] + sdv) - mx);
            uint2 r = *(const uint2*)(hmat + (size_t)s * hstr + coff);
            float2 f0 = __half22float2(*reinterpret_cast<__half2*>(&r.x));
            float2 f1 = __half22float2(*reinterpret_cast<__half2*>(&r.y));
            acc.x += f0.x * p; acc.y += f0.y * p; acc.z += f1.x * p; acc.w += f1.y * p;
        }
    }

    acc.x *= inv; acc.y *= inv; acc.z *= inv; acc.w *= inv;
    int j = h * C + cq * 4;
    float4 bb = *(const float4*)(bias + j);
    acc.x += bb.x; acc.y += bb.y; acc.z += bb.z; acc.w += bb.w;
    if (applyLrelu) {
        acc.x = lrelu(acc.x); acc.y = lrelu(acc.y);
        acc.z = lrelu(acc.z); acc.w = lrelu(acc.w);
    }
    size_t oix = (size_t)n * heads * C + j;
    if (outH) {
        __half2 p0 = __floats2half2_rn(acc.x, acc.y);
        __half2 p1 = __floats2half2_rn(acc.z, acc.w);
        uint2 pk = make_uint2(*reinterpret_cast<uint32_t*>(&p0),
                              *reinterpret_cast<uint32_t*>(&p1));
        *(uint2*)(outH + oix) = pk;
    } else {
        *(float4*)(outF + oix) = acc;
    }
}

// ---------------- batchnorm (fp16 input) -------------------------------------
__global__ void bn_stats_k(const __half* __restrict__ x, float* __restrict__ bn)
{
    int t = threadIdx.x;
    float s0 = 0.f, s1 = 0.f, q0 = 0.f, q1 = 0.f;
    for (int n = blockIdx.x; n < NN; n += gridDim.x) {
        float2 f = __half22float2(*(const __half2*)(x + (size_t)n * H1D + 2 * t));
        s0 += f.x; q0 += f.x * f.x;
        s1 += f.y; q1 += f.y * f.y;
    }
    atomicAdd(bn + 2 * t, s0);       atomicAdd(bn + 2 * t + 1, s1);
    atomicAdd(bn + 512 + 2 * t, q0); atomicAdd(bn + 512 + 2 * t + 1, q1);
}

__global__ void bn_apply_k(const __half* __restrict__ x, const float* __restrict__ bn,
                           const float* __restrict__ gamma, const float* __restrict__ beta,
                           __nv_bfloat16* __restrict__ hi, __nv_bfloat16* __restrict__ lo)
{
    int i = blockIdx.x * blockDim.x + threadIdx.x;
    if (i >= NN * H1D / 2) return;
    int c = (2 * i) & 511;
    const float invN = 1.0f / NN;
    float2 f = __half22float2(*(const __half2*)(x + (size_t)2 * i));
    float mu0 = bn[c] * invN, mu1 = bn[c + 1] * invN;
    float va0 = bn[512 + c] * invN - mu0 * mu0;
    float va1 = bn[512 + c + 1] * invN - mu1 * mu1;
    float v0 = lrelu(gamma[c] * (f.x - mu0) * rsqrtf(va0 + 1e-5f) + beta[c]);
    float v1 = lrelu(gamma[c + 1] * (f.y - mu1) * rsqrtf(va1 + 1e-5f) + beta[c + 1]);
    __nv_bfloat16 h0, l0, h1, l1;
    split_bf(v0, h0, l0); split_bf(v1, h1, l1);
    __nv_bfloat162 hh; hh.x = h0; hh.y = h1;
    __nv_bfloat162 ll; ll.x = l0; ll.y = l1;
    *(__nv_bfloat162*)(hi + (size_t)2 * i) = hh;
    *(__nv_bfloat162*)(lo + (size_t)2 * i) = ll;
}

// ---------------- pooling ----------------------------------------------------
#define PCH 8
__global__ void pool_acc_k(const float* __restrict__ h3, const int* __restrict__ batch,
                           float* __restrict__ out, float* __restrict__ cnt)
{
    int c = threadIdx.x;
    int n0 = blockIdx.x * PCH;
    if (n0 >= NN) return;
    float acc = 0.f, ac = 0.f;
    int curb = batch[n0];
    #pragma unroll
    for (int k = 0; k < PCH; k++) {
        int n = n0 + k;
        if (n >= NN) break;
        int b = batch[n];
        if (b != curb) {
            atomicAdd(out + curb * OUTD + c, acc);
            if (c == 0) atomicAdd(cnt + curb, ac);
            acc = 0.f; ac = 0.f; curb = b;
        }
        acc += h3[(size_t)n * OUTD + c];
        ac += 1.f;
    }
    atomicAdd(out + curb * OUTD + c, acc);
    if (c == 0) atomicAdd(cnt + curb, ac);
}
__global__ void pool_div_k(float* __restrict__ out, const float* __restrict__ cnt)
{
    int i = blockIdx.x * blockDim.x + threadIdx.x;
    if (i >= BB * OUTD) return;
    float c = cnt[i >> 8];
    out[i] /= (c > 1.f ? c : 1.f);
}

// ---------------- host orchestration ----------------------------------------
static inline int ceil_div(int a, int b) { return (a + b - 1) / b; }

extern "C" void kernel_launch(void* const* d_in, const int* in_sizes, int n_in,
                              void* d_out, int out_size)
{
    const float* x      = (const float*)d_in[0];
    const int*   ei     = (const int*)  d_in[1];
    const int*   batch  = (const int*)  d_in[2];
    const float* W1     = (const float*)d_in[3];
    const float* asrc1  = (const float*)d_in[4];
    const float* adst1  = (const float*)d_in[5];
    const float* b1     = (const float*)d_in[6];
    const float* gamma1 = (const float*)d_in[7];
    const float* beta1  = (const float*)d_in[8];
    const float* W2     = (const float*)d_in[9];
    const float* asrc2  = (const float*)d_in[10];
    const float* adst2  = (const float*)d_in[11];
    const float* b2     = (const float*)d_in[12];
    const float* gamma2 = (const float*)d_in[13];
    const float* beta2  = (const float*)d_in[14];
    const float* W3     = (const float*)d_in[15];
    const float* asrc3  = (const float*)d_in[16];
    const float* adst3  = (const float*)d_in[17];
    const float* b3     = (const float*)d_in[18];
    float* out = (float*)d_out;

    float *featB, *ssB, *sdB, *bnB, *cntB;
    __half *hB, *fhB;
    __nv_bfloat16 *ahiB, *aloB, *whiB, *wloB, *whi2B, *wlo2B, *whi3B, *wlo3B;
    cudaGetSymbolAddress((void**)&hB,    g_h);
    cudaGetSymbolAddress((void**)&fhB,   g_fh);
    cudaGetSymbolAddress((void**)&featB, g_feat);
    cudaGetSymbolAddress((void**)&ahiB,  g_ahi);
    cudaGetSymbolAddress((void**)&aloB,  g_alo);
    cudaGetSymbolAddress((void**)&whiB,  g_whi);
    cudaGetSymbolAddress((void**)&wloB,  g_wlo);
    cudaGetSymbolAddress((void**)&whi2B, g_whi2);
    cudaGetSymbolAddress((void**)&wlo2B, g_wlo2);
    cudaGetSymbolAddress((void**)&whi3B, g_whi3);
    cudaGetSymbolAddress((void**)&wlo3B, g_wlo3);
    cudaGetSymbolAddress((void**)&ssB,   g_ssrc);
    cudaGetSymbolAddress((void**)&sdB,   g_sdst);
    cudaGetSymbolAddress((void**)&bnB,   g_bn);
    cudaGetSymbolAddress((void**)&cntB,  g_cnt);

    cudaFuncSetAttribute(gemm_mma_k, cudaFuncAttributeMaxDynamicSharedMemorySize, GEMM_SMEM);

    int rowBlocks = ceil_div(NN, 128);

    // launch 1-3: prep (all 3 W transposes + x split), deg, scan
    prep1_k<<<TALL + SPLBLK, dim3(32, 8)>>>(W1, whiB, wloB, W2, whi2B, wlo2B,
                                            W3, whi3B, wlo3B, x, ahiB, aloB);
    deg_k <<<ceil_div(ET, 256), 256>>>(ei);
    scan_k<<<1, 1024>>>();

    // ================= Layer 1 (gemm = 4th kernel: ncu target) =============
    gemm_mma_k<<<dim3(H1D / 128, rowBlocks), 256, GEMM_SMEM>>>(
        ahiB, aloB, whiB, wloB, hB, NN, IND, H1D, asrc1, adst1, ssB, sdB, NHEADS, 128);
    fill_k<<<ceil_div(ET, 256), 256>>>(ei);
    agg_k<<<NN, NHEADS * (HIDC / 4)>>>(hB, ssB, sdB, b1, nullptr, fhB, NHEADS, HIDC, 0);
    cudaMemsetAsync(bnB, 0, 2 * H1D * sizeof(float));
    bn_stats_k<<<592, 256>>>(fhB, bnB);
    bn_apply_k<<<ceil_div(NN * H1D / 2, 256), 256>>>(fhB, bnB, gamma1, beta1, ahiB, aloB);

    // ================= Layer 2 =================
    gemm_mma_k<<<dim3(H1D / 128, rowBlocks), 256, GEMM_SMEM>>>(
        ahiB, aloB, whi2B, wlo2B, hB, NN, H1D, H1D, asrc2, adst2, ssB, sdB, NHEADS, 128);
    agg_k<<<NN, NHEADS * (HIDC / 4)>>>(hB, ssB, sdB, b2, nullptr, fhB, NHEADS, HIDC, 0);
    cudaMemsetAsync(bnB, 0, 2 * H1D * sizeof(float));
    bn_stats_k<<<592, 256>>>(fhB, bnB);
    bn_apply_k<<<ceil_div(NN * H1D / 2, 256), 256>>>(fhB, bnB, gamma2, beta2, ahiB, aloB);

    // ================= Layer 3 =================
    cudaMemsetAsync(ssB, 0, NN * sizeof(float));
    cudaMemsetAsync(sdB, 0, NN * sizeof(float));
    gemm_mma_k<<<dim3(OUTD / 128, rowBlocks), 256, GEMM_SMEM>>>(
        ahiB, aloB, whi3B, wlo3B, hB, NN, H1D, OUTD, asrc3, adst3, ssB, sdB, 1, 256);
    agg_k<<<NN, OUTD / 4>>>(hB, ssB, sdB, b3, featB, nullptr, 1, OUTD, 1);

    // ================= Global mean pool =================
    cudaMemsetAsync(out, 0, (size_t)BB * OUTD * sizeof(float));
    cudaMemsetAsync(cntB, 0, BB * sizeof(float));
    pool_acc_k<<<ceil_div(NN, PCH), OUTD>>>(featB, batch, out, cntB);
    pool_div_k<<<ceil_div(BB * OUTD, 256), 256>>>(out, cntB);
}